// round 2
// baseline (speedup 1.0000x reference)
#include <cuda_runtime.h>
#include <cstdint>

#define M_ROWS 65536
#define B_ROWS 2048
#define DD 13

// ---- k_mlp shared memory layout (float offsets) ----
// 128-row tile, 512 threads, chunk = 20 j-columns (30 chunks)
#define OFF_W1   0        // [300][14]
#define OFF_B1   4200     // [300]
#define OFF_B2   4500     // [600]
#define OFF_B3   5100     // [112] (zero pad >=100)
#define OFF_B4   5212     // [14], pad to 5232
#define OFF_H1   5232     // [128][308]  (308*4B = 77*16B odd -> conflict-free LDS.128)
#define OFF_W2C  44656    // [20][300]   W2 chunk
#define OFF_H2C  50656    // [128][20]   (20*4B = 5*16B odd -> conflict-free LDS.128)
#define OFF_W3C  53216    // [112][20]   c-major, zero pad c>=100
#define OFF_W4   55456    // [13][112]   zero pad c>=100
#define SMEM_FLOATS 56912
#define SMEM_BYTES  (SMEM_FLOATS * 4)   // 227648 B

// ---- global scratch ----
__device__ float g_t1n[M_ROWS * DD];
__device__ float g_t2n[B_ROWS * DD];
__device__ int   g_maxkey[B_ROWS];

// ---- packed f32x2 helpers ----
__device__ __forceinline__ unsigned long long pk2(float lo, float hi) {
    unsigned long long r;
    asm("mov.b64 %0, {%1,%2};" : "=l"(r) : "f"(lo), "f"(hi));
    return r;
}
__device__ __forceinline__ void upk2(unsigned long long v, float& lo, float& hi) {
    asm("mov.b64 {%0,%1}, %2;" : "=f"(lo), "=f"(hi) : "l"(v));
}
__device__ __forceinline__ void fma2(unsigned long long& d, unsigned long long a,
                                     unsigned long long b) {
    asm("fma.rn.f32x2 %0, %1, %2, %0;" : "+l"(d) : "l"(a), "l"(b));
}

__device__ __forceinline__ int fkey(float f) {
    int i = __float_as_int(f);
    return (i >= 0) ? i : (i ^ 0x7FFFFFFF);
}
__device__ __forceinline__ float finv(int k) {
    return __int_as_float((k >= 0) ? k : (k ^ 0x7FFFFFFF));
}

// ============================================================
__global__ void k_pre(const float* __restrict__ value) {
    int idx = blockIdx.x * blockDim.x + threadIdx.x;
    if (idx < B_ROWS) {
        float v[DD];
        float ss = 0.f;
#pragma unroll
        for (int d = 0; d < DD; d++) { v[d] = value[idx * DD + d]; ss += v[d] * v[d]; }
        float inv = 1.0f / fmaxf(sqrtf(ss), 1e-8f);
#pragma unroll
        for (int d = 0; d < DD; d++) g_t2n[idx * DD + d] = v[d] * inv;
        g_maxkey[idx] = fkey(-3.0e38f);
    }
}

// ============================================================
// k_mlp: fused 4-layer MLP, 128 rows/block, 512 threads, 512 blocks
// ============================================================
__global__ void __launch_bounds__(512)
k_mlp(const float* __restrict__ memory,
      const float* __restrict__ W1, const float* __restrict__ b1,
      const float* __restrict__ W2, const float* __restrict__ b2,
      const float* __restrict__ W3, const float* __restrict__ b3,
      const float* __restrict__ W4, const float* __restrict__ b4) {
    extern __shared__ float sm[];
    const int t = threadIdx.x;
    const int row0 = blockIdx.x * 128;
    const int m = t & 127;        // row within tile (lanes span m -> w reads broadcast)
    const int grp = t >> 7;       // 0..3: j-group (L2) / c-group (L3,L4)
    const int c0 = grp * 28;      // L3 column base (28 c per thread, padded to 112)

    // ---- stage weights/biases ----
    for (int i = t; i < 300 * DD; i += 512) {
        int k = i / DD, d = i % DD;
        sm[OFF_W1 + k * 14 + d] = W1[i];
    }
    for (int i = t; i < 300; i += 512) sm[OFF_B1 + i] = b1[i];
    for (int i = t; i < 600; i += 512) sm[OFF_B2 + i] = b2[i];
    for (int i = t; i < 112; i += 512) sm[OFF_B3 + i] = (i < 100) ? b3[i] : 0.f;
    if (t < 14) sm[OFF_B4 + t] = (t < DD) ? b4[t] : 0.f;
    for (int i = t; i < 13 * 112; i += 512) {
        int d = i / 112, c = i % 112;
        sm[OFF_W4 + i] = (c < 100) ? W4[d * 100 + c] : 0.f;
    }

    // ---- layer 1: h1 = relu(x@W1^T + b1) -> smem [128][308] ----
    {
        float x[DD];
#pragma unroll
        for (int d = 0; d < DD; d++) x[d] = memory[(row0 + m) * DD + d];
        __syncthreads();
        const int k0 = grp * 75;
        for (int k = k0; k < k0 + 75; k++) {
            const float* wr = sm + OFF_W1 + k * 14;   // broadcast (lanes share k)
            float acc = sm[OFF_B1 + k];
#pragma unroll
            for (int d = 0; d < DD; d++) acc += x[d] * wr[d];
            sm[OFF_H1 + m * 308 + k] = fmaxf(acc, 0.f);
        }
    }
    __syncthreads();

    // persistent L3 accumulators (scalar floats -> low register pressure)
    float accf[28];
#pragma unroll
    for (int i = 0; i < 28; i++) accf[i] = 0.f;

    // ---- fused layers 2+3 over 30 chunks of 20 h2-columns ----
    for (int ch = 0; ch < 30; ch++) {
        // stage W2 chunk [20][300]
        const float* W2g = W2 + ch * 20 * 300;
        for (int i = t * 4; i < 6000; i += 2048)
            *reinterpret_cast<float4*>(sm + OFF_W2C + i) =
                *reinterpret_cast<const float4*>(W2g + i);
        // stage W3 chunk c-major [112][20]
        for (int i4 = t; i4 < 560; i4 += 512) {
            int c = i4 / 5, jq = (i4 % 5) * 4;
            float4 v = make_float4(0.f, 0.f, 0.f, 0.f);
            if (c < 100) v = *reinterpret_cast<const float4*>(W3 + c * 600 + ch * 20 + jq);
            *reinterpret_cast<float4*>(sm + OFF_W3C + c * 20 + jq) = v;
        }
        __syncthreads();

        // layer 2: thread = 1 m x 5 j, k-split f32x2 accumulation
        {
            unsigned long long a2[5];
#pragma unroll
            for (int i = 0; i < 5; i++) a2[i] = 0ull;
            const float* hrow  = sm + OFF_H1 + m * 308;
            const float* wbase = sm + OFF_W2C + (grp * 5) * 300;
#pragma unroll 5
            for (int k = 0; k < 300; k += 4) {
                ulonglong2 h = *reinterpret_cast<const ulonglong2*>(hrow + k);
#pragma unroll
                for (int jj = 0; jj < 5; jj++) {
                    ulonglong2 w = *reinterpret_cast<const ulonglong2*>(wbase + jj * 300 + k);
                    fma2(a2[jj], h.x, w.x);
                    fma2(a2[jj], h.y, w.y);
                }
            }
#pragma unroll
            for (int jj = 0; jj < 5; jj++) {
                float lo, hi;
                upk2(a2[jj], lo, hi);
                float z = lo + hi + sm[OFF_B2 + ch * 20 + grp * 5 + jj];
                sm[OFF_H2C + m * 20 + grp * 5 + jj] = (z > 0.f) ? z : 0.01f * z;
            }
        }
        __syncthreads();

        // layer 3: thread = 1 m x 28 c, two half-passes of 14 packed accs
        {
            const float* h2row = sm + OFF_H2C + m * 20;
#pragma unroll
            for (int half = 0; half < 2; half++) {
                const float* w3base = sm + OFF_W3C + (c0 + half * 14) * 20;
                unsigned long long a3[14];
#pragma unroll
                for (int i = 0; i < 14; i++) a3[i] = 0ull;
#pragma unroll
                for (int j = 0; j < 20; j += 4) {
                    ulonglong2 h = *reinterpret_cast<const ulonglong2*>(h2row + j);
#pragma unroll
                    for (int cc = 0; cc < 14; cc++) {
                        ulonglong2 w = *reinterpret_cast<const ulonglong2*>(w3base + cc * 20 + j);
                        fma2(a3[cc], h.x, w.x);
                        fma2(a3[cc], h.y, w.y);
                    }
                }
#pragma unroll
                for (int cc = 0; cc < 14; cc++) {
                    float lo, hi;
                    upk2(a3[cc], lo, hi);
                    accf[half * 14 + cc] += lo + hi;
                }
            }
        }
        __syncthreads();
    }

    // ---- layer 4 partials over this thread's 28 h3 cols ----
    float h3v[28];
#pragma unroll
    for (int cc = 0; cc < 28; cc++) {
        float z = accf[cc] + sm[OFF_B3 + c0 + cc];
        h3v[cc] = fmaxf(z, 0.f);
    }
    unsigned long long pd[DD];
#pragma unroll
    for (int d = 0; d < DD; d++) pd[d] = 0ull;
#pragma unroll
    for (int cp = 0; cp < 14; cp++) {
        unsigned long long hp = pk2(h3v[2 * cp], h3v[2 * cp + 1]);
#pragma unroll
        for (int d = 0; d < DD; d++)
            fma2(pd[d], hp,
                 *reinterpret_cast<const unsigned long long*>(sm + OFF_W4 + d * 112 + c0 + 2 * cp));
    }
#pragma unroll
    for (int d = 0; d < DD; d++) {
        float lo, hi;
        upk2(pd[d], lo, hi);
        sm[OFF_H1 + (m * 4 + grp) * 14 + d] = lo + hi;  // h1 region is dead now
    }
    __syncthreads();

    // ---- reduce partials, leaky, normalize, write t1n ----
    if (t < 128) {
        float t1v[DD];
        float ss = 0.f;
#pragma unroll
        for (int d = 0; d < DD; d++) {
            float s_ = sm[OFF_H1 + (t * 4 + 0) * 14 + d]
                     + sm[OFF_H1 + (t * 4 + 1) * 14 + d]
                     + sm[OFF_H1 + (t * 4 + 2) * 14 + d]
                     + sm[OFF_H1 + (t * 4 + 3) * 14 + d];
            s_ += sm[OFF_B4 + d];
            float v = (s_ > 0.f) ? s_ : 0.01f * s_;
            t1v[d] = v;
            ss += v * v;
        }
        float inv = 1.0f / fmaxf(sqrtf(ss), 1e-8f);
#pragma unroll
        for (int d = 0; d < DD; d++)
            g_t1n[(row0 + t) * DD + d] = t1v[d] * inv;
    }
}

// ============================================================
// k_sim: per-b running max over a 512-row m tile
// ============================================================
__global__ void __launch_bounds__(256) k_sim() {
    __shared__ float sT[DD * 512];  // d-major
    const int t  = threadIdx.x;
    const int m0 = blockIdx.x * 512;
    const int b  = blockIdx.y * 256 + t;

    for (int i = t; i < 512 * DD; i += 256) {
        int mm = i / DD, d = i % DD;
        sT[d * 512 + mm] = g_t1n[(m0 + mm) * DD + d];
    }
    unsigned long long q[DD];
#pragma unroll
    for (int d = 0; d < DD; d++) {
        float v = g_t2n[b * DD + d];
        q[d] = pk2(v, v);
    }
    __syncthreads();

    float mx = -3.0e38f;
#pragma unroll 2
    for (int mp = 0; mp < 512; mp += 2) {
        unsigned long long acc = 0ull;
#pragma unroll
        for (int d = 0; d < DD; d++)
            fma2(acc, q[d], *reinterpret_cast<const unsigned long long*>(&sT[d * 512 + mp]));
        float lo, hi;
        upk2(acc, lo, hi);
        mx = fmaxf(mx, fmaxf(lo, hi));
    }
    atomicMax(&g_maxkey[b], fkey(mx));
}

// ============================================================
__global__ void k_fin(float* __restrict__ out) {
    int b = blockIdx.x * blockDim.x + threadIdx.x;
    if (b < B_ROWS) out[b] = 23.0f * finv(g_maxkey[b]);
}

// ============================================================
extern "C" void kernel_launch(void* const* d_in, const int* in_sizes, int n_in,
                              void* d_out, int out_size) {
    const float* memory = (const float*)d_in[0];
    const float* value  = (const float*)d_in[1];
    const float* W1 = (const float*)d_in[2];
    const float* b1 = (const float*)d_in[3];
    const float* W2 = (const float*)d_in[4];
    const float* b2 = (const float*)d_in[5];
    const float* W3 = (const float*)d_in[6];
    const float* b3 = (const float*)d_in[7];
    const float* W4 = (const float*)d_in[8];
    const float* b4 = (const float*)d_in[9];

    cudaFuncSetAttribute(k_mlp, cudaFuncAttributeMaxDynamicSharedMemorySize, SMEM_BYTES);

    k_pre<<<8, 256>>>(value);
    k_mlp<<<512, 512, SMEM_BYTES>>>(memory, W1, b1, W2, b2, W3, b3, W4, b4);
    k_sim<<<dim3(128, 8), 256>>>();
    k_fin<<<8, 256>>>((float*)d_out);
}

// round 3
// speedup vs baseline: 1.3266x; 1.3266x over previous
#include <cuda_runtime.h>
#include <cstdint>

#define M_ROWS 65536
#define B_ROWS 2048
#define DD 13

// ---- k_mlp smem layout (float offsets), 64-row tile, 256 threads ----
#define OFF_B2   0        // [600]
#define OFF_B3   600      // [112] zero pad >=100
#define OFF_B4   712      // [16]  zero pad >=13
#define OFF_H1   728      // [64][308]   (1232B stride: 80i mod 128 distinct)
#define OFF_W2C  20440    // [40][300]   W2 chunk; W1 [300][14] aliased pre-loop
#define OFF_H2C  32440    // [64][44]    (176B stride: 48i mod 128 distinct)
#define OFF_W3C  35256    // [112][44]   c-major, zero pad c>=100; B1 aliased pre-loop
#define OFF_W4   40184    // [13][112]   zero pad c>=100
#define SMEM_FLOATS 41640
#define SMEM_BYTES  (SMEM_FLOATS * 4)   // 166560 B

// ---- global scratch ----
__device__ float g_t1n[M_ROWS * DD];
__device__ float g_t2n[B_ROWS * DD];
__device__ int   g_maxkey[B_ROWS];

// ---- packed f32x2 helpers ----
__device__ __forceinline__ unsigned long long pk2(float lo, float hi) {
    unsigned long long r;
    asm("mov.b64 %0, {%1,%2};" : "=l"(r) : "f"(lo), "f"(hi));
    return r;
}
__device__ __forceinline__ void upk2(unsigned long long v, float& lo, float& hi) {
    asm("mov.b64 {%0,%1}, %2;" : "=f"(lo), "=f"(hi) : "l"(v));
}
__device__ __forceinline__ void fma2(unsigned long long& d, unsigned long long a,
                                     unsigned long long b) {
    asm("fma.rn.f32x2 %0, %1, %2, %0;" : "+l"(d) : "l"(a), "l"(b));
}

__device__ __forceinline__ int fkey(float f) {
    int i = __float_as_int(f);
    return (i >= 0) ? i : (i ^ 0x7FFFFFFF);
}
__device__ __forceinline__ float finv(int k) {
    return __int_as_float((k >= 0) ? k : (k ^ 0x7FFFFFFF));
}

// ============================================================
__global__ void k_pre(const float* __restrict__ value) {
    int idx = blockIdx.x * blockDim.x + threadIdx.x;
    if (idx < B_ROWS) {
        float v[DD];
        float ss = 0.f;
#pragma unroll
        for (int d = 0; d < DD; d++) { v[d] = value[idx * DD + d]; ss += v[d] * v[d]; }
        float inv = 1.0f / fmaxf(sqrtf(ss), 1e-8f);
#pragma unroll
        for (int d = 0; d < DD; d++) g_t2n[idx * DD + d] = v[d] * inv;
        g_maxkey[idx] = fkey(-3.0e38f);
    }
}

// ============================================================
// k_mlp: fused 4-layer MLP. 64 rows/block, 256 threads, 1024 blocks.
// Warp lane grid: 8 m-lanes x 4 j-lanes; per-thread tile Rm=2.
// ============================================================
__global__ void __launch_bounds__(256)
k_mlp(const float* __restrict__ memory,
      const float* __restrict__ W1, const float* __restrict__ b1,
      const float* __restrict__ W2, const float* __restrict__ b2,
      const float* __restrict__ W3, const float* __restrict__ b3,
      const float* __restrict__ W4, const float* __restrict__ b4) {
    extern __shared__ float sm[];
    const int t = threadIdx.x;
    const int row0 = blockIdx.x * 64;

    const int warp = t >> 5;
    const int wm = warp & 3;          // m-block of 16
    const int wj = warp >> 2;         // 0..1: j-half (L2) / c-half (L3)
    const int l  = t & 31;
    const int lm = l & 7;             // 8 m-lanes
    const int lj = l >> 3;            // 4 j-lanes
    const int mA = wm * 16 + lm;      // this thread's rows
    const int mB = mA + 8;
    const int jb = wj * 20 + lj * 5;  // L2: 5 j's starting here (within chunk)
    const int cb = wj * 56 + lj * 14; // L3/L4: 14 c's starting here (c padded to 112)

    // ---- stage persistent small tables ----
    for (int i = t; i < 600; i += 256) sm[OFF_B2 + i] = b2[i];
    for (int i = t; i < 112; i += 256) sm[OFF_B3 + i] = (i < 100) ? b3[i] : 0.f;
    if (t < 16) sm[OFF_B4 + t] = (t < DD) ? b4[t] : 0.f;
    for (int i = t; i < 13 * 112; i += 256) {
        int d = i / 112, c = i % 112;
        sm[OFF_W4 + i] = (c < 100) ? W4[d * 100 + c] : 0.f;
    }
    // W1 -> aliased into W2C region as [300][14]; b1 -> aliased into W3C region
    for (int i = t; i < 300 * DD; i += 256) {
        int k = i / DD, d = i % DD;
        sm[OFF_W2C + k * 14 + d] = W1[i];
    }
    for (int i = t; i < 300; i += 256) sm[OFF_W3C + i] = b1[i];

    // ---- layer 1: h1 = relu(x@W1^T + b1) -> smem [64][308] ----
    {
        const int m = t & 63;
        const int kg = t >> 6;        // 4 groups x 75 k
        float x[DD];
#pragma unroll
        for (int d = 0; d < DD; d++) x[d] = memory[(row0 + m) * DD + d];
        __syncthreads();  // staging done
        for (int k = kg * 75; k < kg * 75 + 75; k++) {
            const float* wr = sm + OFF_W2C + k * 14;   // broadcast
            float acc = sm[OFF_W3C + k];
#pragma unroll
            for (int d = 0; d < DD; d++) acc += x[d] * wr[d];
            sm[OFF_H1 + m * 308 + k] = fmaxf(acc, 0.f);
        }
    }
    __syncthreads();

    // persistent L3 accumulators (scalars, folded per chunk)
    float accf[2][14];
#pragma unroll
    for (int r = 0; r < 2; r++)
#pragma unroll
        for (int i = 0; i < 14; i++) accf[r][i] = 0.f;

    // ---- fused layers 2+3, 15 chunks of 40 h2 columns ----
    for (int ch = 0; ch < 15; ch++) {
        // stage W2 chunk [40][300]
        {
            const float4* W2g = reinterpret_cast<const float4*>(W2 + ch * 40 * 300);
            float4* dst = reinterpret_cast<float4*>(sm + OFF_W2C);
            for (int i = t; i < 3000; i += 256) dst[i] = W2g[i];
        }
        // stage W3 chunk c-major [112][44-stride], zero pad c>=100
        for (int i4 = t; i4 < 1120; i4 += 256) {
            int c = i4 / 10, jq = (i4 % 10) * 4;
            float4 v = make_float4(0.f, 0.f, 0.f, 0.f);
            if (c < 100) v = *reinterpret_cast<const float4*>(W3 + c * 600 + ch * 40 + jq);
            *reinterpret_cast<float4*>(sm + OFF_W3C + c * 44 + jq) = v;
        }
        __syncthreads();

        // ---- layer 2: thread = 2m x 5j, k-split f32x2 ----
        {
            unsigned long long a2[2][5];
#pragma unroll
            for (int r = 0; r < 2; r++)
#pragma unroll
                for (int i = 0; i < 5; i++) a2[r][i] = 0ull;
            const float* hA = sm + OFF_H1 + mA * 308;
            const float* hB = sm + OFF_H1 + mB * 308;
            const float* wb = sm + OFF_W2C + jb * 300;
#pragma unroll 5
            for (int k = 0; k < 300; k += 4) {
                ulonglong2 ha = *reinterpret_cast<const ulonglong2*>(hA + k);
                ulonglong2 hb = *reinterpret_cast<const ulonglong2*>(hB + k);
#pragma unroll
                for (int jj = 0; jj < 5; jj++) {
                    ulonglong2 w = *reinterpret_cast<const ulonglong2*>(wb + jj * 300 + k);
                    fma2(a2[0][jj], ha.x, w.x);
                    fma2(a2[0][jj], ha.y, w.y);
                    fma2(a2[1][jj], hb.x, w.x);
                    fma2(a2[1][jj], hb.y, w.y);
                }
            }
#pragma unroll
            for (int jj = 0; jj < 5; jj++) {
                float bias = sm[OFF_B2 + ch * 40 + jb + jj];
                float lo, hi;
                upk2(a2[0][jj], lo, hi);
                float zA = lo + hi + bias;
                sm[OFF_H2C + mA * 44 + jb + jj] = (zA > 0.f) ? zA : 0.01f * zA;
                upk2(a2[1][jj], lo, hi);
                float zB = lo + hi + bias;
                sm[OFF_H2C + mB * 44 + jb + jj] = (zB > 0.f) ? zB : 0.01f * zB;
            }
        }
        __syncthreads();

        // ---- layer 3: thread = 2m x 14c, j-split f32x2, fold to scalars ----
        {
            unsigned long long a3[2][14];
#pragma unroll
            for (int r = 0; r < 2; r++)
#pragma unroll
                for (int i = 0; i < 14; i++) a3[r][i] = 0ull;
            const float* h2A = sm + OFF_H2C + mA * 44;
            const float* h2B = sm + OFF_H2C + mB * 44;
            const float* w3b = sm + OFF_W3C + cb * 44;
#pragma unroll 2
            for (int j = 0; j < 40; j += 4) {
                ulonglong2 ha = *reinterpret_cast<const ulonglong2*>(h2A + j);
                ulonglong2 hb = *reinterpret_cast<const ulonglong2*>(h2B + j);
#pragma unroll
                for (int cc = 0; cc < 14; cc++) {
                    ulonglong2 w = *reinterpret_cast<const ulonglong2*>(w3b + cc * 44 + j);
                    fma2(a3[0][cc], ha.x, w.x);
                    fma2(a3[0][cc], ha.y, w.y);
                    fma2(a3[1][cc], hb.x, w.x);
                    fma2(a3[1][cc], hb.y, w.y);
                }
            }
#pragma unroll
            for (int cc = 0; cc < 14; cc++) {
                float lo, hi;
                upk2(a3[0][cc], lo, hi);
                accf[0][cc] += lo + hi;
                upk2(a3[1][cc], lo, hi);
                accf[1][cc] += lo + hi;
            }
        }
        __syncthreads();
    }

    // ---- layer 4 partials: thread covers (mA,mB) x 14 c at cb ----
    {
        const int p = wj * 4 + lj;     // 8 partials per m
#pragma unroll
        for (int r = 0; r < 2; r++) {
            const int m = (r == 0) ? mA : mB;
            float h3v[14];
#pragma unroll
            for (int cc = 0; cc < 14; cc++)
                h3v[cc] = fmaxf(accf[r][cc] + sm[OFF_B3 + cb + cc], 0.f);
            unsigned long long pd[DD];
#pragma unroll
            for (int d = 0; d < DD; d++) pd[d] = 0ull;
#pragma unroll
            for (int cp = 0; cp < 7; cp++) {
                unsigned long long hp = pk2(h3v[2 * cp], h3v[2 * cp + 1]);
#pragma unroll
                for (int d = 0; d < DD; d++)
                    fma2(pd[d], hp, *reinterpret_cast<const unsigned long long*>(
                                        sm + OFF_W4 + d * 112 + cb + 2 * cp));
            }
#pragma unroll
            for (int d = 0; d < DD; d++) {
                float lo, hi;
                upk2(pd[d], lo, hi);
                sm[OFF_H1 + (m * 8 + p) * 14 + d] = lo + hi;  // h1 dead
            }
        }
    }
    __syncthreads();

    // ---- reduce 8 partials per row, bias, leaky, normalize, store t1n ----
    if (t < 64) {
        float t1v[DD];
        float ss = 0.f;
#pragma unroll
        for (int d = 0; d < DD; d++) {
            float s_ = sm[OFF_B4 + d];
#pragma unroll
            for (int p = 0; p < 8; p++) s_ += sm[OFF_H1 + (t * 8 + p) * 14 + d];
            float v = (s_ > 0.f) ? s_ : 0.01f * s_;
            t1v[d] = v;
            ss += v * v;
        }
        float inv = 1.0f / fmaxf(sqrtf(ss), 1e-8f);
#pragma unroll
        for (int d = 0; d < DD; d++)
            g_t1n[(row0 + t) * DD + d] = t1v[d] * inv;
    }
}

// ============================================================
// k_sim: per-b running max over a 512-row m tile
// ============================================================
__global__ void __launch_bounds__(256) k_sim() {
    __shared__ float sT[DD * 512];  // d-major
    const int t  = threadIdx.x;
    const int m0 = blockIdx.x * 512;
    const int b  = blockIdx.y * 256 + t;

    for (int i = t; i < 512 * DD; i += 256) {
        int mm = i / DD, d = i % DD;
        sT[d * 512 + mm] = g_t1n[(m0 + mm) * DD + d];
    }
    unsigned long long q[DD];
#pragma unroll
    for (int d = 0; d < DD; d++) {
        float v = g_t2n[b * DD + d];
        q[d] = pk2(v, v);
    }
    __syncthreads();

    float mx = -3.0e38f;
#pragma unroll 2
    for (int mp = 0; mp < 512; mp += 2) {
        unsigned long long acc = 0ull;
#pragma unroll
        for (int d = 0; d < DD; d++)
            fma2(acc, q[d], *reinterpret_cast<const unsigned long long*>(&sT[d * 512 + mp]));
        float lo, hi;
        upk2(acc, lo, hi);
        mx = fmaxf(mx, fmaxf(lo, hi));
    }
    atomicMax(&g_maxkey[b], fkey(mx));
}

// ============================================================
__global__ void k_fin(float* __restrict__ out) {
    int b = blockIdx.x * blockDim.x + threadIdx.x;
    if (b < B_ROWS) out[b] = 23.0f * finv(g_maxkey[b]);
}

// ============================================================
extern "C" void kernel_launch(void* const* d_in, const int* in_sizes, int n_in,
                              void* d_out, int out_size) {
    const float* memory = (const float*)d_in[0];
    const float* value  = (const float*)d_in[1];
    const float* W1 = (const float*)d_in[2];
    const float* b1 = (const float*)d_in[3];
    const float* W2 = (const float*)d_in[4];
    const float* b2 = (const float*)d_in[5];
    const float* W3 = (const float*)d_in[6];
    const float* b3 = (const float*)d_in[7];
    const float* W4 = (const float*)d_in[8];
    const float* b4 = (const float*)d_in[9];

    cudaFuncSetAttribute(k_mlp, cudaFuncAttributeMaxDynamicSharedMemorySize, SMEM_BYTES);

    k_pre<<<8, 256>>>(value);
    k_mlp<<<1024, 256, SMEM_BYTES>>>(memory, W1, b1, W2, b2, W3, b3, W4, b4);
    k_sim<<<dim3(128, 8), 256>>>();
    k_fin<<<8, 256>>>((float*)d_out);
}

// round 5
// speedup vs baseline: 2.7752x; 2.0919x over previous
#include <cuda_runtime.h>
#include <cuda_bf16.h>
#include <cstdint>

#define M_ROWS 65536
#define B_ROWS 2048
#define DD 13
#define K1P 320     // padded h1 width (K of layer2)
#define N2P 640     // padded h2 width
#define N3P 128     // padded W3 rows (h3 width)

// ---------- global scratch ----------
__device__ __nv_bfloat16 g_h1hi[(size_t)M_ROWS * K1P];
__device__ __nv_bfloat16 g_h1lo[(size_t)M_ROWS * K1P];
__device__ __nv_bfloat16 g_h2hi[(size_t)M_ROWS * N2P];
__device__ __nv_bfloat16 g_h2lo[(size_t)M_ROWS * N2P];
__device__ __nv_bfloat16 g_w2hi[N2P * K1P];
__device__ __nv_bfloat16 g_w2lo[N2P * K1P];
__device__ __nv_bfloat16 g_w3hi[N3P * N2P];
__device__ __nv_bfloat16 g_w3lo[N3P * N2P];
__device__ float g_t1n[(size_t)M_ROWS * DD];
__device__ float g_t2n[B_ROWS * DD];
__device__ int   g_maxkey[B_ROWS];

// ---------- helpers ----------
__device__ __forceinline__ uint32_t smem_u32(const void* p) {
    uint32_t a;
    asm("{ .reg .u64 t; cvta.to.shared.u64 t, %1; cvt.u32.u64 %0, t; }" : "=r"(a) : "l"(p));
    return a;
}
__device__ __forceinline__ void ldm_x4(uint32_t& r0, uint32_t& r1, uint32_t& r2,
                                       uint32_t& r3, uint32_t addr) {
    asm volatile("ldmatrix.sync.aligned.m8n8.x4.shared.b16 {%0,%1,%2,%3}, [%4];"
                 : "=r"(r0), "=r"(r1), "=r"(r2), "=r"(r3) : "r"(addr));
}
__device__ __forceinline__ void mma_bf16(float* c, const uint32_t* a,
                                         uint32_t b0, uint32_t b1) {
    asm volatile(
        "mma.sync.aligned.m16n8k16.row.col.f32.bf16.bf16.f32 "
        "{%0,%1,%2,%3}, {%4,%5,%6,%7}, {%8,%9}, {%0,%1,%2,%3};"
        : "+f"(c[0]), "+f"(c[1]), "+f"(c[2]), "+f"(c[3])
        : "r"(a[0]), "r"(a[1]), "r"(a[2]), "r"(a[3]), "r"(b0), "r"(b1));
}
__device__ __forceinline__ int fkey(float f) {
    int i = __float_as_int(f);
    return (i >= 0) ? i : (i ^ 0x7FFFFFFF);
}
__device__ __forceinline__ float finv(int k) {
    return __int_as_float((k >= 0) ? k : (k ^ 0x7FFFFFFF));
}
__device__ __forceinline__ void bsplit(float v, __nv_bfloat16& hi, __nv_bfloat16& lo) {
    hi = __float2bfloat16(v);
    lo = __float2bfloat16(v - __bfloat162float(hi));
}
__device__ __forceinline__ unsigned long long pk2(float lo, float hi) {
    unsigned long long r;
    asm("mov.b64 %0, {%1,%2};" : "=l"(r) : "f"(lo), "f"(hi));
    return r;
}
__device__ __forceinline__ void upk2(unsigned long long v, float& lo, float& hi) {
    asm("mov.b64 {%0,%1}, %2;" : "=f"(lo), "=f"(hi) : "l"(v));
}
__device__ __forceinline__ void fma2(unsigned long long& d, unsigned long long a,
                                     unsigned long long b) {
    asm("fma.rn.f32x2 %0, %1, %2, %0;" : "+l"(d) : "l"(a), "l"(b));
}

// ============================================================
// k_prep: split W2 / W3 into zero-padded bf16 hi/lo planes
// ============================================================
__global__ void k_prep(const float* __restrict__ W2, const float* __restrict__ W3) {
    const int stride = gridDim.x * blockDim.x;
    for (int i = blockIdx.x * blockDim.x + threadIdx.x; i < N2P * K1P; i += stride) {
        int n = i / K1P, k = i % K1P;
        float v = (n < 600 && k < 300) ? W2[n * 300 + k] : 0.f;
        __nv_bfloat16 h, l; bsplit(v, h, l);
        g_w2hi[i] = h; g_w2lo[i] = l;
    }
    for (int i = blockIdx.x * blockDim.x + threadIdx.x; i < N3P * N2P; i += stride) {
        int c = i / N2P, k = i % N2P;
        float v = (c < 100 && k < 600) ? W3[c * 600 + k] : 0.f;
        __nv_bfloat16 h, l; bsplit(v, h, l);
        g_w3hi[i] = h; g_w3lo[i] = l;
    }
}

// ============================================================
__global__ void k_pre(const float* __restrict__ value) {
    int idx = blockIdx.x * blockDim.x + threadIdx.x;
    if (idx < B_ROWS) {
        float v[DD]; float ss = 0.f;
#pragma unroll
        for (int d = 0; d < DD; d++) { v[d] = value[idx * DD + d]; ss += v[d] * v[d]; }
        float inv = 1.0f / fmaxf(sqrtf(ss), 1e-8f);
#pragma unroll
        for (int d = 0; d < DD; d++) g_t2n[idx * DD + d] = v[d] * inv;
        g_maxkey[idx] = fkey(-3.0e38f);
    }
}

// ============================================================
// k_l1: layer1 fp32, split-store h1 bf16 planes (64 rows/block)
// ============================================================
#define L1_SMEM ((4200 + 300 + 64 * 304) * 4)
__global__ void __launch_bounds__(256)
k_l1(const float* __restrict__ memory, const float* __restrict__ W1,
     const float* __restrict__ b1) {
    extern __shared__ float sf[];
    const int t = threadIdx.x;
    const int row0 = blockIdx.x * 64;
    for (int i = t; i < 300 * DD; i += 256) { int k = i / DD, d = i % DD; sf[k * 14 + d] = W1[i]; }
    for (int i = t; i < 300; i += 256) sf[4200 + i] = b1[i];
    const int m = t & 63, kg = t >> 6;
    float x[DD];
#pragma unroll
    for (int d = 0; d < DD; d++) x[d] = memory[(row0 + m) * DD + d];
    __syncthreads();
    for (int k = kg * 75; k < kg * 75 + 75; k++) {
        const float* wr = sf + k * 14;
        float acc = sf[4200 + k];
#pragma unroll
        for (int d = 0; d < DD; d++) acc += x[d] * wr[d];
        sf[4500 + m * 304 + k] = fmaxf(acc, 0.f);
    }
    __syncthreads();
    for (int i = t; i < 64 * 160; i += 256) {
        int row = i / 160, kp = (i % 160) * 2;
        float v0 = (kp < 300) ? sf[4500 + row * 304 + kp] : 0.f;
        float v1 = (kp + 1 < 300) ? sf[4500 + row * 304 + kp + 1] : 0.f;
        __nv_bfloat16 h0, l0, h1, l1;
        bsplit(v0, h0, l0); bsplit(v1, h1, l1);
        __nv_bfloat162 ph; ph.x = h0; ph.y = h1;
        __nv_bfloat162 pl; pl.x = l0; pl.y = l1;
        size_t o = (size_t)(row0 + row) * K1P + kp;
        *reinterpret_cast<__nv_bfloat162*>(g_h1hi + o) = ph;
        *reinterpret_cast<__nv_bfloat162*>(g_h1lo + o) = pl;
    }
}

// ============================================================
// k_l2: h2 = leaky(h1 @ W2^T + b2) via mma.sync bf16 3-term split.
// CTA 128x128, K=320 in 5 chunks of 64. grid (512, 5), 256 thr.
// smem bytes: bias @0 [128]f; A_HI @1024 (18432 = 128 rows x 72 bf16);
//   A_LO @19456; B_HI @37888; B_LO @56320; total 74752.
//   Epilogue reuse: EPI_HI @1024 (32768), EPI_LO @33792 (32768).
// ============================================================
#define L2_AHI 1024
#define L2_ALO 19456
#define L2_BHI 37888
#define L2_BLO 56320
#define L2_EHI 1024
#define L2_ELO 33792
#define L2_SMEM 74752
#define PLANE 18432
__global__ void __launch_bounds__(256, 2)
k_l2(const float* __restrict__ b2) {
    extern __shared__ char smc[];
    const uint32_t sb = smem_u32(smc);
    float* biasS = reinterpret_cast<float*>(smc);
    const int t = threadIdx.x, warp = t >> 5, lane = t & 31;
    const int m0 = blockIdx.x * 128, n0 = blockIdx.y * 128;
    const int m_warp = (warp & 3) * 32, n_warp = (warp >> 2) * 64;

    for (int i = t; i < 128; i += 256) { int j = n0 + i; biasS[i] = (j < 600) ? b2[j] : 0.f; }

    // per-lane ldmatrix base addresses (k-offset added per step)
    uint32_t aB[2], bB[4];
#pragma unroll
    for (int f = 0; f < 2; f++) {
        int r = m_warp + f * 16 + (lane & 7) + ((lane >> 3) & 1) * 8;
        aB[f] = sb + L2_AHI + r * 144 + (lane >> 4) * 16;
    }
#pragma unroll
    for (int bp = 0; bp < 4; bp++) {
        int r = n_warp + bp * 16 + (lane & 7) + (lane >> 4) * 8;
        bB[bp] = sb + L2_BHI + r * 144 + ((lane >> 3) & 1) * 16;
    }

    float acc[2][8][4];
#pragma unroll
    for (int f = 0; f < 2; f++)
#pragma unroll
        for (int n = 0; n < 8; n++)
#pragma unroll
            for (int q = 0; q < 4; q++) acc[f][n][q] = 0.f;

    for (int ch = 0; ch < 5; ch++) {
        const int kc = ch * 64;
        __syncthreads();   // previous chunk's mma done before overwrite
        // stage A planes (hi at +0, lo at +PLANE)
        for (int i = t; i < 2048; i += 256) {
            int pl = i >> 10, r = (i >> 3) & 127, cc = i & 7;
            const char* src = pl ? (const char*)g_h1lo : (const char*)g_h1hi;
            *reinterpret_cast<float4*>(smc + L2_AHI + pl * PLANE + r * 144 + cc * 16) =
                *reinterpret_cast<const float4*>(src + ((size_t)(m0 + r) * K1P + kc + cc * 8) * 2);
        }
        // stage B planes
        for (int i = t; i < 2048; i += 256) {
            int pl = i >> 10, r = (i >> 3) & 127, cc = i & 7;
            const char* src = pl ? (const char*)g_w2lo : (const char*)g_w2hi;
            *reinterpret_cast<float4*>(smc + L2_BHI + pl * PLANE + r * 144 + cc * 16) =
                *reinterpret_cast<const float4*>(src + ((size_t)(n0 + r) * K1P + kc + cc * 8) * 2);
        }
        __syncthreads();

#pragma unroll
        for (int ks = 0; ks < 4; ks++) {
            const uint32_t ko = ks * 32;
            uint32_t aH[2][4], aL[2][4];
#pragma unroll
            for (int f = 0; f < 2; f++) {
                ldm_x4(aH[f][0], aH[f][1], aH[f][2], aH[f][3], aB[f] + ko);
                ldm_x4(aL[f][0], aL[f][1], aL[f][2], aL[f][3], aB[f] + PLANE + ko);
            }
#pragma unroll
            for (int bp = 0; bp < 4; bp++) {
                uint32_t bH[4], bL[4];
                ldm_x4(bH[0], bH[1], bH[2], bH[3], bB[bp] + ko);
                ldm_x4(bL[0], bL[1], bL[2], bL[3], bB[bp] + PLANE + ko);
#pragma unroll
                for (int f = 0; f < 2; f++) {
#pragma unroll
                    for (int h = 0; h < 2; h++) {
                        float* c = acc[f][bp * 2 + h];
                        mma_bf16(c, aH[f], bH[2 * h], bH[2 * h + 1]);
                        mma_bf16(c, aH[f], bL[2 * h], bL[2 * h + 1]);
                        mma_bf16(c, aL[f], bH[2 * h], bH[2 * h + 1]);
                    }
                }
            }
        }
    }
    __syncthreads();

    // epilogue: bias + leaky + split -> smem planes
#pragma unroll
    for (int f = 0; f < 2; f++) {
        int r0 = m_warp + f * 16 + (lane >> 2);
#pragma unroll
        for (int nf = 0; nf < 8; nf++) {
            int col = n_warp + nf * 8 + (lane & 3) * 2;
            float b0 = biasS[col], b1 = biasS[col + 1];
            const float* c = acc[f][nf];
#pragma unroll
            for (int hrow = 0; hrow < 2; hrow++) {
                int r = r0 + hrow * 8;
                float z0 = c[2 * hrow] + b0, z1 = c[2 * hrow + 1] + b1;
                z0 = (z0 > 0.f) ? z0 : 0.01f * z0;
                z1 = (z1 > 0.f) ? z1 : 0.01f * z1;
                __nv_bfloat16 h0, l0, h1, l1;
                bsplit(z0, h0, l0); bsplit(z1, h1, l1);
                __nv_bfloat162 vh; vh.x = h0; vh.y = h1;
                __nv_bfloat162 vl; vl.x = l0; vl.y = l1;
                *reinterpret_cast<__nv_bfloat162*>(smc + L2_EHI + r * 256 + col * 2) = vh;
                *reinterpret_cast<__nv_bfloat162*>(smc + L2_ELO + r * 256 + col * 2) = vl;
            }
        }
    }
    __syncthreads();
    // coalesced global writes
    for (int i = t; i < 2048; i += 256) {
        int r = i >> 4, cc = i & 15;
        *reinterpret_cast<float4*>((char*)g_h2hi + ((size_t)(m0 + r) * N2P + n0) * 2 + cc * 16) =
            *reinterpret_cast<const float4*>(smc + L2_EHI + r * 256 + cc * 16);
        *reinterpret_cast<float4*>((char*)g_h2lo + ((size_t)(m0 + r) * N2P + n0) * 2 + cc * 16) =
            *reinterpret_cast<const float4*>(smc + L2_ELO + r * 256 + cc * 16);
    }
}

// ============================================================
// k_l3: h3 = relu(h2 @ W3^T + b3), fused layer4 + leaky + normalize.
// CTA 128x128, K=640 in 10 chunks. grid 512, 256 thr.
// smem: W4s @64 (5824B = [13][112]f), b3s @5888 (512), b4s @6400 (64);
//   A_HI @6656; A_LO @25088; B_HI @43520; B_LO @61952; total 80384.
//   Epilogue h3 fp32 [128][129] @6656 (66048B, reuses A/B region).
// ============================================================
#define L3_AHI 6656
#define L3_ALO 25088
#define L3_BHI 43520
#define L3_BLO 61952
#define L3_H3  6656
#define L3_SMEM 80384
__global__ void __launch_bounds__(256, 2)
k_l3(const float* __restrict__ b3, const float* __restrict__ b4,
     const float* __restrict__ W4) {
    extern __shared__ char smc[];
    const uint32_t sb = smem_u32(smc);
    float* W4s = reinterpret_cast<float*>(smc + 64);
    float* b3s = reinterpret_cast<float*>(smc + 5888);
    float* b4s = reinterpret_cast<float*>(smc + 6400);
    const int t = threadIdx.x, warp = t >> 5, lane = t & 31;
    const int m0 = blockIdx.x * 128;
    const int m_warp = (warp & 3) * 32, n_warp = (warp >> 2) * 64;

    for (int i = t; i < 13 * 112; i += 256) {
        int d = i / 112, c = i % 112;
        W4s[i] = (c < 100) ? W4[d * 100 + c] : 0.f;
    }
    for (int i = t; i < 128; i += 256) b3s[i] = (i < 100) ? b3[i] : 0.f;
    if (t < 16) b4s[t] = (t < DD) ? b4[t] : 0.f;

    uint32_t aB[2], bB[4];
#pragma unroll
    for (int f = 0; f < 2; f++) {
        int r = m_warp + f * 16 + (lane & 7) + ((lane >> 3) & 1) * 8;
        aB[f] = sb + L3_AHI + r * 144 + (lane >> 4) * 16;
    }
#pragma unroll
    for (int bp = 0; bp < 4; bp++) {
        int r = n_warp + bp * 16 + (lane & 7) + (lane >> 4) * 8;
        bB[bp] = sb + L3_BHI + r * 144 + ((lane >> 3) & 1) * 16;
    }

    float acc[2][8][4];
#pragma unroll
    for (int f = 0; f < 2; f++)
#pragma unroll
        for (int n = 0; n < 8; n++)
#pragma unroll
            for (int q = 0; q < 4; q++) acc[f][n][q] = 0.f;

    for (int ch = 0; ch < 10; ch++) {
        const int kc = ch * 64;
        __syncthreads();
        for (int i = t; i < 2048; i += 256) {
            int pl = i >> 10, r = (i >> 3) & 127, cc = i & 7;
            const char* src = pl ? (const char*)g_h2lo : (const char*)g_h2hi;
            *reinterpret_cast<float4*>(smc + L3_AHI + pl * PLANE + r * 144 + cc * 16) =
                *reinterpret_cast<const float4*>(src + ((size_t)(m0 + r) * N2P + kc + cc * 8) * 2);
        }
        for (int i = t; i < 2048; i += 256) {
            int pl = i >> 10, r = (i >> 3) & 127, cc = i & 7;
            const char* src = pl ? (const char*)g_w3lo : (const char*)g_w3hi;
            *reinterpret_cast<float4*>(smc + L3_BHI + pl * PLANE + r * 144 + cc * 16) =
                *reinterpret_cast<const float4*>(src + ((size_t)r * N2P + kc + cc * 8) * 2);
        }
        __syncthreads();

#pragma unroll
        for (int ks = 0; ks < 4; ks++) {
            const uint32_t ko = ks * 32;
            uint32_t aH[2][4], aL[2][4];
#pragma unroll
            for (int f = 0; f < 2; f++) {
                ldm_x4(aH[f][0], aH[f][1], aH[f][2], aH[f][3], aB[f] + ko);
                ldm_x4(aL[f][0], aL[f][1], aL[f][2], aL[f][3], aB[f] + PLANE + ko);
            }
#pragma unroll
            for (int bp = 0; bp < 4; bp++) {
                uint32_t bH[4], bL[4];
                ldm_x4(bH[0], bH[1], bH[2], bH[3], bB[bp] + ko);
                ldm_x4(bL[0], bL[1], bL[2], bL[3], bB[bp] + PLANE + ko);
#pragma unroll
                for (int f = 0; f < 2; f++) {
#pragma unroll
                    for (int h = 0; h < 2; h++) {
                        float* c = acc[f][bp * 2 + h];
                        mma_bf16(c, aH[f], bH[2 * h], bH[2 * h + 1]);
                        mma_bf16(c, aH[f], bL[2 * h], bL[2 * h + 1]);
                        mma_bf16(c, aL[f], bH[2 * h], bH[2 * h + 1]);
                    }
                }
            }
        }
    }
    __syncthreads();

    // epilogue: h3 = relu(acc + b3) -> smem fp32 [128][129]
    float* h3 = reinterpret_cast<float*>(smc + L3_H3);
#pragma unroll
    for (int f = 0; f < 2; f++) {
        int r0 = m_warp + f * 16 + (lane >> 2);
#pragma unroll
        for (int nf = 0; nf < 8; nf++) {
            int col = n_warp + nf * 8 + (lane & 3) * 2;
            const float* c = acc[f][nf];
#pragma unroll
            for (int hrow = 0; hrow < 2; hrow++) {
                int r = r0 + hrow * 8;
                h3[r * 129 + col]     = fmaxf(c[2 * hrow] + b3s[col], 0.f);
                h3[r * 129 + col + 1] = fmaxf(c[2 * hrow + 1] + b3s[col + 1], 0.f);
            }
        }
    }
    __syncthreads();

    // layer4 + leaky + normalize per row
    if (t < 128) {
        const float* hr = h3 + t * 129;
        float t1[DD];
#pragma unroll
        for (int d = 0; d < DD; d++) t1[d] = b4s[d];
        for (int c = 0; c < 100; c++) {
            float h = hr[c];
#pragma unroll
            for (int d = 0; d < DD; d++) t1[d] += h * W4s[d * 112 + c];
        }
        float ss = 0.f;
#pragma unroll
        for (int d = 0; d < DD; d++) {
            float v = (t1[d] > 0.f) ? t1[d] : 0.01f * t1[d];
            t1[d] = v;
            ss += v * v;
        }
        float inv = 1.0f / fmaxf(sqrtf(ss), 1e-8f);
#pragma unroll
        for (int d = 0; d < DD; d++) g_t1n[(size_t)(m0 + t) * DD + d] = t1[d] * inv;
    }
}

// ============================================================
// k_sim: per-b running max over a 512-row m tile
// ============================================================
__global__ void __launch_bounds__(256) k_sim() {
    __shared__ float sT[DD * 512];
    const int t = threadIdx.x;
    const int m0 = blockIdx.x * 512;
    const int b = blockIdx.y * 256 + t;

    for (int i = t; i < 512 * DD; i += 256) {
        int mm = i / DD, d = i % DD;
        sT[d * 512 + mm] = g_t1n[(size_t)(m0 + mm) * DD + d];
    }
    unsigned long long q[DD];
#pragma unroll
    for (int d = 0; d < DD; d++) {
        float v = g_t2n[b * DD + d];
        q[d] = pk2(v, v);
    }
    __syncthreads();

    float mx = -3.0e38f;
#pragma unroll 2
    for (int mp = 0; mp < 512; mp += 2) {
        unsigned long long acc = 0ull;
#pragma unroll
        for (int d = 0; d < DD; d++)
            fma2(acc, q[d], *reinterpret_cast<const unsigned long long*>(&sT[d * 512 + mp]));
        float lo, hi;
        upk2(acc, lo, hi);
        mx = fmaxf(mx, fmaxf(lo, hi));
    }
    atomicMax(&g_maxkey[b], fkey(mx));
}

// ============================================================
__global__ void k_fin(float* __restrict__ out) {
    int b = blockIdx.x * blockDim.x + threadIdx.x;
    if (b < B_ROWS) out[b] = 23.0f * finv(g_maxkey[b]);
}

// ============================================================
extern "C" void kernel_launch(void* const* d_in, const int* in_sizes, int n_in,
                              void* d_out, int out_size) {
    const float* memory = (const float*)d_in[0];
    const float* value  = (const float*)d_in[1];
    const float* W1 = (const float*)d_in[2];
    const float* b1 = (const float*)d_in[3];
    const float* W2 = (const float*)d_in[4];
    const float* b2 = (const float*)d_in[5];
    const float* W3 = (const float*)d_in[6];
    const float* b3 = (const float*)d_in[7];
    const float* W4 = (const float*)d_in[8];
    const float* b4 = (const float*)d_in[9];

    cudaFuncSetAttribute(k_l1, cudaFuncAttributeMaxDynamicSharedMemorySize, L1_SMEM);
    cudaFuncSetAttribute(k_l2, cudaFuncAttributeMaxDynamicSharedMemorySize, L2_SMEM);
    cudaFuncSetAttribute(k_l3, cudaFuncAttributeMaxDynamicSharedMemorySize, L3_SMEM);

    k_prep<<<512, 256>>>(W2, W3);
    k_pre<<<8, 256>>>(value);
    k_l1<<<1024, 256, L1_SMEM>>>(memory, W1, b1);
    k_l2<<<dim3(512, 5), 256, L2_SMEM>>>(b2);
    k_l3<<<512, 256, L3_SMEM>>>(b3, b4, W4);
    k_sim<<<dim3(128, 8), 256>>>();
    k_fin<<<8, 256>>>((float*)d_out);
}